// round 1
// baseline (speedup 1.0000x reference)
#include <cuda_runtime.h>
#include <cstdint>

#define B_   256
#define T_   2048
#define IN_  128
#define H_   64
#define G_   256   // 4*H

// Scratch (allocation-free rule: static __device__ arrays)
__device__ float g_xp[(size_t)B_ * T_ * G_];   // precomputed x@W_ih1^T + b_ih1 + b_hh1
__device__ float g_Wt[IN_ * G_];               // W_ih1 transposed: [k][g]

// ---------------- helpers ----------------
__device__ __forceinline__ void ffma2(unsigned long long& d, unsigned long long a,
                                      unsigned long long b) {
    asm("fma.rn.f32x2 %0, %1, %2, %0;" : "+l"(d) : "l"(a), "l"(b));
}
__device__ __forceinline__ float2 unpk(unsigned long long p) {
    float2 r;
    asm("mov.b64 {%0, %1}, %2;" : "=f"(r.x), "=f"(r.y) : "l"(p));
    return r;
}
__device__ __forceinline__ unsigned long long dup2(float a) {
    unsigned long long r;
    asm("mov.b64 %0, {%1, %1};" : "=l"(r) : "f"(a));
    return r;
}
__device__ __forceinline__ float sigf(float x) {
    return __fdividef(1.0f, 1.0f + __expf(-x));
}
__device__ __forceinline__ float tanhf_(float x) {
    float a = fabsf(x);
    float e = __expf(2.0f * a);                 // inf-safe: 2/(inf+1) -> 0
    float r = 1.0f - __fdividef(2.0f, e + 1.0f);
    return copysignf(r, x);
}

// ---------------- kernel 1: transpose W_ih1 into k-major ----------------
__global__ void wt_kernel(const float* __restrict__ W) {
    int i = blockIdx.x * 256 + threadIdx.x;    // 32768 elems
    int n = i >> 7;
    int k = i & 127;
    g_Wt[k * G_ + n] = W[n * IN_ + k];
}

// ---------------- kernel 2: xp = x @ W_ih1^T + b_ih1 + b_hh1 ----------------
// M = B*T = 524288, N = 256, K = 128. BM=64, BN=64, 256 threads, 4x4 tile,
// n-paired f32x2 accumulation. W streamed from g_Wt (L1-resident per-ntile).
__global__ __launch_bounds__(256) void xp_gemm(const float* __restrict__ x,
                                               const float* __restrict__ bih,
                                               const float* __restrict__ bhh) {
    __shared__ float Xs[64][128];              // 32 KB
    int tid = threadIdx.x;
    size_t mbase = (size_t)blockIdx.x * 64;
    int nbase = blockIdx.y * 64;

    const float* xg = x + mbase * IN_;
#pragma unroll
    for (int i = 0; i < 8; i++) {              // 64*128 floats = 2048 float4
        int idx = tid + i * 256;
        int m = idx >> 5, k4 = (idx & 31) << 2;
        *(float4*)&Xs[m][k4] = *(const float4*)(xg + m * IN_ + k4);
    }
    __syncthreads();

    int tx = tid & 15, ty = tid >> 4;
    int n0 = nbase + tx * 4;
    int m0 = ty * 4;

    unsigned long long acc[4][2];
#pragma unroll
    for (int i = 0; i < 4; i++) { acc[i][0] = 0ull; acc[i][1] = 0ull; }

    const float* wt = g_Wt + n0;
#pragma unroll 8
    for (int k = 0; k < IN_; k++) {
        ulonglong2 bb = *(const ulonglong2*)(wt + k * G_);   // LDG.128, L1 hit
#pragma unroll
        for (int i = 0; i < 4; i++) {
            unsigned long long ap = dup2(Xs[m0 + i][k]);     // broadcast LDS
            ffma2(acc[i][0], ap, bb.x);
            ffma2(acc[i][1], ap, bb.y);
        }
    }

    float4 bs;
    bs.x = bih[n0 + 0] + bhh[n0 + 0];
    bs.y = bih[n0 + 1] + bhh[n0 + 1];
    bs.z = bih[n0 + 2] + bhh[n0 + 2];
    bs.w = bih[n0 + 3] + bhh[n0 + 3];
#pragma unroll
    for (int i = 0; i < 4; i++) {
        float2 p0 = unpk(acc[i][0]);
        float2 p1 = unpk(acc[i][1]);
        float4 o = make_float4(p0.x + bs.x, p0.y + bs.y, p1.x + bs.z, p1.y + bs.w);
        *(float4*)(g_xp + (mbase + m0 + i) * G_ + n0) = o;
    }
}

// ---------------- kernel 3: fused 2-layer LSTM recurrence + output head ----------------
// 128 CTAs x 512 threads, 1 CTA/SM, 2 batch rows per CTA.
// thread tid: g = tid>>1 (gate row 0..255), half = tid&1 (which 32-wide half of the dot).
// All recurrent weights live in registers as f32x2 pairs (packed along k).
__global__ __launch_bounds__(512, 1) void lstm_rec(
    const float* __restrict__ Whh1, const float* __restrict__ Wih2,
    const float* __restrict__ Whh2, const float* __restrict__ bih2,
    const float* __restrict__ bhh2, const float* __restrict__ Wout,
    const float* __restrict__ bout, float* __restrict__ out) {
    __shared__ float h1s[2][64];
    __shared__ float h2s[2][64];
    __shared__ float ga[2][256];
    __shared__ float gb[2][256];
    __shared__ float red[4];

    int tid = threadIdx.x;
    int g = tid >> 1, half = tid & 1;

    // weight rows (k-paired as f32x2): 48 x 64-bit = 96 regs
    unsigned long long w1[16], w2i[16], w2h[16];
    {
        const unsigned long long* p =
            (const unsigned long long*)(Whh1 + g * 64 + half * 32);
#pragma unroll
        for (int j = 0; j < 16; j++) w1[j] = p[j];
        p = (const unsigned long long*)(Wih2 + g * 64 + half * 32);
#pragma unroll
        for (int j = 0; j < 16; j++) w2i[j] = p[j];
        p = (const unsigned long long*)(Whh2 + g * 64 + half * 32);
#pragma unroll
        for (int j = 0; j < 16; j++) w2h[j] = p[j];
    }
    float bias2 = bih2[g] + bhh2[g];

    int urow = tid >> 6, uk = tid & 63;        // valid when tid < 128
    float wo = (tid < 128) ? Wout[uk] : 0.0f;
    float bo = bout[0];
    float c1v = 0.0f, c2v = 0.0f;

    if (tid < 128) { h1s[urow][uk] = 0.0f; h2s[urow][uk] = 0.0f; }
    __syncthreads();

    int b0 = blockIdx.x * 2;
    const float* xp0 = g_xp + (size_t)b0 * T_ * G_ + g;
    const float* xp1 = xp0 + (size_t)T_ * G_;
    float xc0 = 0.0f, xc1 = 0.0f;
    if (half == 0) { xc0 = xp0[0]; xc1 = xp1[0]; }

    const ulonglong2* h1p0 = (const ulonglong2*)&h1s[0][half * 32];
    const ulonglong2* h1p1 = (const ulonglong2*)&h1s[1][half * 32];
    const ulonglong2* h2p0 = (const ulonglong2*)&h2s[0][half * 32];
    const ulonglong2* h2p1 = (const ulonglong2*)&h2s[1][half * 32];

    for (int t = 0; t < T_; t++) {
        // ---- phase 1: layer-1 recurrent gates ----
        unsigned long long a0 = 0ull, a1 = 0ull;
#pragma unroll
        for (int q = 0; q < 8; q++) {
            ulonglong2 u0 = h1p0[q];
            ulonglong2 u1 = h1p1[q];
            ffma2(a0, w1[2 * q], u0.x); ffma2(a0, w1[2 * q + 1], u0.y);
            ffma2(a1, w1[2 * q], u1.x); ffma2(a1, w1[2 * q + 1], u1.y);
        }
        float2 f0 = unpk(a0), f1 = unpk(a1);
        float s0 = f0.x + f0.y, s1 = f1.x + f1.y;
        s0 += __shfl_xor_sync(0xffffffffu, s0, 1);
        s1 += __shfl_xor_sync(0xffffffffu, s1, 1);
        if (half == 0) {
            ga[0][g] = s0 + xc0;
            ga[1][g] = s1 + xc1;
            if (t + 1 < T_) {                  // prefetch next step's xp
                xc0 = xp0[(t + 1) * G_];
                xc1 = xp1[(t + 1) * G_];
            }
        }
        __syncthreads();

        // ---- update 1: activations, c1/h1 ----
        if (tid < 128) {
            float iv = sigf(ga[urow][uk]);
            float fv = sigf(ga[urow][64 + uk]);
            float gv = tanhf_(ga[urow][128 + uk]);
            float ov = sigf(ga[urow][192 + uk]);
            c1v = fv * c1v + iv * gv;
            h1s[urow][uk] = ov * tanhf_(c1v);
        }
        __syncthreads();

        // ---- phase 2: layer-2 gates = W_ih2 @ h1_new + W_hh2 @ h2_prev ----
        a0 = 0ull; a1 = 0ull;
#pragma unroll
        for (int q = 0; q < 8; q++) {
            ulonglong2 u0 = h1p0[q];
            ulonglong2 u1 = h1p1[q];
            ffma2(a0, w2i[2 * q], u0.x); ffma2(a0, w2i[2 * q + 1], u0.y);
            ffma2(a1, w2i[2 * q], u1.x); ffma2(a1, w2i[2 * q + 1], u1.y);
        }
#pragma unroll
        for (int q = 0; q < 8; q++) {
            ulonglong2 u0 = h2p0[q];
            ulonglong2 u1 = h2p1[q];
            ffma2(a0, w2h[2 * q], u0.x); ffma2(a0, w2h[2 * q + 1], u0.y);
            ffma2(a1, w2h[2 * q], u1.x); ffma2(a1, w2h[2 * q + 1], u1.y);
        }
        f0 = unpk(a0); f1 = unpk(a1);
        s0 = f0.x + f0.y; s1 = f1.x + f1.y;
        s0 += __shfl_xor_sync(0xffffffffu, s0, 1);
        s1 += __shfl_xor_sync(0xffffffffu, s1, 1);
        if (half == 0) {
            gb[0][g] = s0 + bias2;
            gb[1][g] = s1 + bias2;
        }
        __syncthreads();

        // ---- update 2: c2/h2 + output-head partial reduction ----
        if (tid < 128) {
            float iv = sigf(gb[urow][uk]);
            float fv = sigf(gb[urow][64 + uk]);
            float gv = tanhf_(gb[urow][128 + uk]);
            float ov = sigf(gb[urow][192 + uk]);
            c2v = fv * c2v + iv * gv;
            float h2v = ov * tanhf_(c2v);
            h2s[urow][uk] = h2v;
            float p = wo * h2v;
#pragma unroll
            for (int off = 16; off > 0; off >>= 1)
                p += __shfl_xor_sync(0xffffffffu, p, off);
            if ((tid & 31) == 0) red[tid >> 5] = p;
        }
        __syncthreads();

        if (tid < 2) {
            float r = red[2 * tid] + red[2 * tid + 1] + bo;
            r = fminf(fmaxf(r, 0.0f), 1.0f);
            out[(size_t)(b0 + tid) * T_ + t] = r;
        }
    }
}

// ---------------- launch ----------------
extern "C" void kernel_launch(void* const* d_in, const int* in_sizes, int n_in,
                              void* d_out, int out_size) {
    const float* x    = (const float*)d_in[0];
    const float* Wih1 = (const float*)d_in[1];
    const float* Whh1 = (const float*)d_in[2];
    const float* bih1 = (const float*)d_in[3];
    const float* bhh1 = (const float*)d_in[4];
    const float* Wih2 = (const float*)d_in[5];
    const float* Whh2 = (const float*)d_in[6];
    const float* bih2 = (const float*)d_in[7];
    const float* bhh2 = (const float*)d_in[8];
    const float* Wout = (const float*)d_in[9];
    const float* bout = (const float*)d_in[10];
    float* out = (float*)d_out;

    wt_kernel<<<128, 256>>>(Wih1);
    xp_gemm<<<dim3((B_ * T_) / 64, G_ / 64), 256>>>(x, bih1, bhh1);
    lstm_rec<<<128, 512>>>(Whh1, Wih2, Whh2, bih2, bhh2, Wout, bout, out);
    (void)in_sizes; (void)n_in; (void)out_size;
}

// round 2
// speedup vs baseline: 1.0673x; 1.0673x over previous
#include <cuda_runtime.h>
#include <cstdint>

#define B_   256
#define T_   2048
#define IN_  128
#define H_   64
#define G_   256   // 4*H

// Scratch (allocation-free rule: static __device__ arrays)
__device__ float g_xp[(size_t)B_ * T_ * G_];   // precomputed x@W_ih1^T + b_ih1 + b_hh1
__device__ float g_Wt[IN_ * G_];               // W_ih1 transposed: [k][g]

typedef unsigned long long u64;

// ---------------- helpers ----------------
__device__ __forceinline__ void ffma2(u64& d, u64 a, u64 b) {
    asm("fma.rn.f32x2 %0, %1, %2, %0;" : "+l"(d) : "l"(a), "l"(b));
}
__device__ __forceinline__ float2 unpk(u64 p) {
    float2 r;
    asm("mov.b64 {%0, %1}, %2;" : "=f"(r.x), "=f"(r.y) : "l"(p));
    return r;
}
__device__ __forceinline__ u64 dup2(float a) {
    u64 r;
    asm("mov.b64 %0, {%1, %1};" : "=l"(r) : "f"(a));
    return r;
}
__device__ __forceinline__ float sigf(float x) {
    return __fdividef(1.0f, 1.0f + __expf(-x));
}
__device__ __forceinline__ float tanhf_(float x) {
    float a = fabsf(x);
    float e = __expf(2.0f * a);                 // inf-safe
    float r = 1.0f - __fdividef(2.0f, e + 1.0f);
    return copysignf(r, x);
}

// ---------------- kernel 1: transpose W_ih1 into k-major ----------------
__global__ void wt_kernel(const float* __restrict__ W) {
    int i = blockIdx.x * 256 + threadIdx.x;    // 32768 elems
    int n = i >> 7;
    int k = i & 127;
    g_Wt[k * G_ + n] = W[n * IN_ + k];
}

// ---------------- kernel 2: xp = x @ W_ih1^T + b_ih1 + b_hh1 ----------------
__global__ __launch_bounds__(256) void xp_gemm(const float* __restrict__ x,
                                               const float* __restrict__ bih,
                                               const float* __restrict__ bhh) {
    __shared__ float Xs[64][128];              // 32 KB
    int tid = threadIdx.x;
    size_t mbase = (size_t)blockIdx.x * 64;
    int nbase = blockIdx.y * 64;

    const float* xg = x + mbase * IN_;
#pragma unroll
    for (int i = 0; i < 8; i++) {
        int idx = tid + i * 256;
        int m = idx >> 5, k4 = (idx & 31) << 2;
        *(float4*)&Xs[m][k4] = *(const float4*)(xg + m * IN_ + k4);
    }
    __syncthreads();

    int tx = tid & 15, ty = tid >> 4;
    int n0 = nbase + tx * 4;
    int m0 = ty * 4;

    u64 acc[4][2];
#pragma unroll
    for (int i = 0; i < 4; i++) { acc[i][0] = 0ull; acc[i][1] = 0ull; }

    const float* wt = g_Wt + n0;
#pragma unroll 8
    for (int k = 0; k < IN_; k++) {
        ulonglong2 bb = *(const ulonglong2*)(wt + k * G_);
#pragma unroll
        for (int i = 0; i < 4; i++) {
            u64 ap = dup2(Xs[m0 + i][k]);
            ffma2(acc[i][0], ap, bb.x);
            ffma2(acc[i][1], ap, bb.y);
        }
    }

    float4 bs;
    bs.x = bih[n0 + 0] + bhh[n0 + 0];
    bs.y = bih[n0 + 1] + bhh[n0 + 1];
    bs.z = bih[n0 + 2] + bhh[n0 + 2];
    bs.w = bih[n0 + 3] + bhh[n0 + 3];
#pragma unroll
    for (int i = 0; i < 4; i++) {
        float2 p0 = unpk(acc[i][0]);
        float2 p1 = unpk(acc[i][1]);
        float4 o = make_float4(p0.x + bs.x, p0.y + bs.y, p1.x + bs.z, p1.y + bs.w);
        *(float4*)(g_xp + (mbase + m0 + i) * G_ + n0) = o;
    }
}

// ---------------- kernel 3: fused 2-layer LSTM recurrence + output head ----------------
// 128 CTAs x 256 threads, 2 batch rows per CTA (both rows per thread).
// Thread tid: q = tid>>2 (gate quad, gates 4q..4q+3), s = tid&3 (K split).
//   Layer-1 dot: k in [16s, 16s+16)  over h1 (64).
//   Layer-2 dot: kcat in [32s, 32s+32) over concat [h1new(64); h2prev(64)].
// Weights in registers: 4*16 + 4*32 = 192 floats = 96 x f32x2 regs.
// Gate partial sums combined with 2 shfl_xor (s-butterfly); gate sums go to smem;
// dedicated 128 threads do activations (1 MUFU warp per SMSP).
__global__ __launch_bounds__(256, 1) void lstm_rec(
    const float* __restrict__ Whh1, const float* __restrict__ Wih2,
    const float* __restrict__ Whh2, const float* __restrict__ bih2,
    const float* __restrict__ bhh2, const float* __restrict__ Wout,
    const float* __restrict__ bout, float* __restrict__ out) {
    __shared__ float h1s[2][2][64];   // [buf][row][unit]
    __shared__ float h2s[2][2][64];
    __shared__ float ga[2][256];      // [row][gate]
    __shared__ float gb[2][256];
    __shared__ float red[4];

    int tid = threadIdx.x;
    int q = tid >> 2, s = tid & 3;
    int g0 = q * 4;

    // ---- load weights into registers ----
    u64 w1[4][8];    // [gate][k-pair]  k in [16s,16s+16)
    u64 w2[4][16];   // [gate][kc-pair] kcat in [32s,32s+32)
#pragma unroll
    for (int g = 0; g < 4; g++) {
        const u64* p1 = (const u64*)(Whh1 + (g0 + g) * 64 + s * 16);
#pragma unroll
        for (int j = 0; j < 8; j++) w1[g][j] = p1[j];
        const float* b2 = (s < 2) ? (Wih2 + (g0 + g) * 64 + s * 32)
                                  : (Whh2 + (g0 + g) * 64 + (s - 2) * 32);
        const u64* p2 = (const u64*)b2;
#pragma unroll
        for (int j = 0; j < 16; j++) w2[g][j] = p2[j];
    }
    float4 bias2v;
    bias2v.x = bih2[g0 + 0] + bhh2[g0 + 0];
    bias2v.y = bih2[g0 + 1] + bhh2[g0 + 1];
    bias2v.z = bih2[g0 + 2] + bhh2[g0 + 2];
    bias2v.w = bih2[g0 + 3] + bhh2[g0 + 3];

    // update-thread state (tid < 128): row ur, unit uu
    int ur = tid >> 6, uu = tid & 63;
    float wo = (tid < 128) ? Wout[uu] : 0.0f;
    float bo = bout[0];
    float c1v = 0.0f, c2v = 0.0f;

    // zero both h buffers
    ((float*)h1s)[tid] = 0.0f;
    ((float*)h2s)[tid] = 0.0f;
    __syncthreads();

    int b0 = blockIdx.x * 2;
    const float* xpb0 = g_xp + (size_t)b0 * T_ * G_ + g0;
    const float* xpb1 = xpb0 + (size_t)T_ * G_;
    float4 xq0 = make_float4(0, 0, 0, 0), xq1 = xq0;
    if (s == 0) {
        xq0 = *(const float4*)xpb0;
        xq1 = *(const float4*)xpb1;
    }

    for (int t = 0; t < T_; t++) {
        int cur = t & 1, prv = cur ^ 1;

        // ---- P1: layer-1 recurrent gates ----
        u64 a[8];   // [g*2 + row]
#pragma unroll
        for (int i = 0; i < 8; i++) a[i] = 0ull;
        {
            const ulonglong2* hA = (const ulonglong2*)&h1s[prv][0][s * 16];
            const ulonglong2* hB = (const ulonglong2*)&h1s[prv][1][s * 16];
#pragma unroll
            for (int j = 0; j < 4; j++) {
                ulonglong2 u0 = hA[j];
                ulonglong2 u1 = hB[j];
#pragma unroll
                for (int g = 0; g < 4; g++) {
                    ffma2(a[2 * g + 0], w1[g][2 * j], u0.x);
                    ffma2(a[2 * g + 0], w1[g][2 * j + 1], u0.y);
                    ffma2(a[2 * g + 1], w1[g][2 * j], u1.x);
                    ffma2(a[2 * g + 1], w1[g][2 * j + 1], u1.y);
                }
            }
        }
        float v[8];
#pragma unroll
        for (int i = 0; i < 8; i++) {
            float2 f = unpk(a[i]);
            v[i] = f.x + f.y;
            v[i] += __shfl_xor_sync(0xffffffffu, v[i], 1);
            v[i] += __shfl_xor_sync(0xffffffffu, v[i], 2);
        }
        if (s == 0) {
            float4 r0 = make_float4(v[0] + xq0.x, v[2] + xq0.y, v[4] + xq0.z, v[6] + xq0.w);
            float4 r1 = make_float4(v[1] + xq1.x, v[3] + xq1.y, v[5] + xq1.z, v[7] + xq1.w);
            *(float4*)&ga[0][g0] = r0;
            *(float4*)&ga[1][g0] = r1;
            if (t + 1 < T_) {                   // prefetch next step's xp
                xq0 = *(const float4*)(xpb0 + (size_t)(t + 1) * G_);
                xq1 = *(const float4*)(xpb1 + (size_t)(t + 1) * G_);
            }
        }
        __syncthreads();

        // ---- U1: layer-1 activations ----
        if (tid < 128) {
            float iv = sigf(ga[ur][uu]);
            float fv = sigf(ga[ur][64 + uu]);
            float gv = tanhf_(ga[ur][128 + uu]);
            float ov = sigf(ga[ur][192 + uu]);
            c1v = fv * c1v + iv * gv;
            h1s[cur][ur][uu] = ov * tanhf_(c1v);
        }
        __syncthreads();

        // ---- P2: layer-2 gates over concat [h1new; h2prev] ----
#pragma unroll
        for (int i = 0; i < 8; i++) a[i] = 0ull;
        {
            const ulonglong2* pA;
            const ulonglong2* pB;
            if (s < 2) {
                pA = (const ulonglong2*)&h1s[cur][0][s * 32];
                pB = (const ulonglong2*)&h1s[cur][1][s * 32];
            } else {
                pA = (const ulonglong2*)&h2s[prv][0][(s - 2) * 32];
                pB = (const ulonglong2*)&h2s[prv][1][(s - 2) * 32];
            }
#pragma unroll
            for (int j = 0; j < 8; j++) {
                ulonglong2 u0 = pA[j];
                ulonglong2 u1 = pB[j];
#pragma unroll
                for (int g = 0; g < 4; g++) {
                    ffma2(a[2 * g + 0], w2[g][2 * j], u0.x);
                    ffma2(a[2 * g + 0], w2[g][2 * j + 1], u0.y);
                    ffma2(a[2 * g + 1], w2[g][2 * j], u1.x);
                    ffma2(a[2 * g + 1], w2[g][2 * j + 1], u1.y);
                }
            }
        }
#pragma unroll
        for (int i = 0; i < 8; i++) {
            float2 f = unpk(a[i]);
            v[i] = f.x + f.y;
            v[i] += __shfl_xor_sync(0xffffffffu, v[i], 1);
            v[i] += __shfl_xor_sync(0xffffffffu, v[i], 2);
        }
        if (s == 0) {
            float4 r0 = make_float4(v[0] + bias2v.x, v[2] + bias2v.y,
                                    v[4] + bias2v.z, v[6] + bias2v.w);
            float4 r1 = make_float4(v[1] + bias2v.x, v[3] + bias2v.y,
                                    v[5] + bias2v.z, v[7] + bias2v.w);
            *(float4*)&gb[0][g0] = r0;
            *(float4*)&gb[1][g0] = r1;
        }
        __syncthreads();

        // ---- U2: layer-2 activations + output-head partials ----
        if (tid < 128) {
            float iv = sigf(gb[ur][uu]);
            float fv = sigf(gb[ur][64 + uu]);
            float gv = tanhf_(gb[ur][128 + uu]);
            float ov = sigf(gb[ur][192 + uu]);
            c2v = fv * c2v + iv * gv;
            float h2v = ov * tanhf_(c2v);
            h2s[cur][ur][uu] = h2v;
            float p = wo * h2v;
#pragma unroll
            for (int off = 16; off > 0; off >>= 1)
                p += __shfl_xor_sync(0xffffffffu, p, off);
            if ((tid & 31) == 0) red[tid >> 5] = p;
        }
        __syncthreads();

        if (tid < 2) {
            float r = red[2 * tid] + red[2 * tid + 1] + bo;
            r = fminf(fmaxf(r, 0.0f), 1.0f);
            out[(size_t)(b0 + tid) * T_ + t] = r;
        }
    }
}

// ---------------- launch ----------------
extern "C" void kernel_launch(void* const* d_in, const int* in_sizes, int n_in,
                              void* d_out, int out_size) {
    const float* x    = (const float*)d_in[0];
    const float* Wih1 = (const float*)d_in[1];
    const float* Whh1 = (const float*)d_in[2];
    const float* bih1 = (const float*)d_in[3];
    const float* bhh1 = (const float*)d_in[4];
    const float* Wih2 = (const float*)d_in[5];
    const float* Whh2 = (const float*)d_in[6];
    const float* bih2 = (const float*)d_in[7];
    const float* bhh2 = (const float*)d_in[8];
    const float* Wout = (const float*)d_in[9];
    const float* bout = (const float*)d_in[10];
    float* out = (float*)d_out;

    wt_kernel<<<128, 256>>>(Wih1);
    xp_gemm<<<dim3((B_ * T_) / 64, G_ / 64), 256>>>(x, bih1, bhh1);
    lstm_rec<<<128, 256>>>(Whh1, Wih2, Whh2, bih2, bhh2, Wout, bout, out);
    (void)in_sizes; (void)n_in; (void)out_size;
}